// round 12
// baseline (speedup 1.0000x reference)
#include <cuda_runtime.h>
#include <math.h>

#define C_CH   192
#define HW     56
#define NPIX   3136      // 56*56
#define NBATCH 64
#define NPLANE 12288     // 64*192
#define NCELL  602112    // 12288*49
#define N4TOT  9633792   // 64*192*3136/4
#define PPB    2
#define POOLBLK (NPLANE / PPB)   // 6144
#define FCHUNK 1024              // float4 per final block
#define FBLK   (N4TOT / FCHUNK)  // 9408

__constant__ float c_lowx[32] = {0,0,1,1,0,2,2,1,2,0,3,4,0,1,3,0,1,2,3,4,5,0,1,2,3,4,5,6,1,2,3,4};
__constant__ float c_lowy[32] = {0,1,0,1,2,0,1,2,2,3,0,0,4,3,1,5,4,3,2,1,0,6,5,4,3,2,1,0,6,5,4,3};

// Scratch (no allocations allowed -> __device__ globals)
__device__ float g_part[56 * 32];        // per-row gate partial sums (n=0 only)
__device__ float g_xp[NCELL];            // adaptive-avg-pooled x
__device__ float g_w1dT[192 * 192];      // transposed center tap of w1d: [c][o]
__device__ float g_scale[NPLANE];        // final per-(n,c) scale

// ---------------------------------------------------------------------------
// Fused gate+pool kernel, occupancy 4 (<=36 regs; gate path proven to fit 32,
// pool path may spill ~1-2 regs -- negligible vs +33% in-flight bytes).
//   blocks 0..55     : gate conv for batch element 0, one block per image row.
//   blocks 56..6199  : pool, 2 planes per block, 4 independent warp-contiguous
//                      LDG.128 per thread, one sync, 98-thread reduce.
// ---------------------------------------------------------------------------
__global__ __launch_bounds__(448, 4) void poolgate_kernel(
    const float* __restrict__ x, const float* __restrict__ wg1,
    const float* __restrict__ bng, const float* __restrict__ bnb,
    const float* __restrict__ bnm, const float* __restrict__ bnv,
    const float* __restrict__ w1d)
{
    __shared__ float smem[192 * 32 + 56 * 33];
    int t = threadIdx.x;
    int b = blockIdx.x;

    if (b < 56) {
        // ---------------- gate path (batch element 0 only) ----------------
        float* sw    = smem;             // [192*32] sw[c*32+o] = wg1[o][c]
        float* sconv = smem + 192 * 32;  // [56*33] padded

        for (int i = t; i < 192 * 32; i += 448) {
            int c = i >> 5, o = i & 31;
            sw[i] = wg1[o * 192 + c];
        }
        for (int i = t; i < 56 * 33; i += 448) sconv[i] = 0.0f;
        __syncthreads();

        int px = t % 56;
        int q  = t / 56;
        const float* xr = x + b * 56 + px;
        float* dst = sconv + px * 33;
        int c0 = q * 24;

        for (int pass = 0; pass < 4; pass++) {
            int o0 = pass * 8;
            float acc[8];
#pragma unroll
            for (int u = 0; u < 8; u++) acc[u] = 0.0f;
#pragma unroll 4
            for (int c = c0; c < c0 + 24; c++) {
                float xv = __ldg(xr + c * NPIX);      // pass>0: L1 hit
                const float* w = sw + c * 32 + o0;
#pragma unroll
                for (int u = 0; u < 8; u++) acc[u] = fmaf(w[u], xv, acc[u]);
            }
#pragma unroll
            for (int u = 0; u < 8; u++) atomicAdd(dst + o0 + u, acc[u]);
        }
        __syncthreads();

        if (t < 32) {
            int o = t;
            float sc = bng[o] / sqrtf(bnv[o] + 1e-5f);
            float sh = bnb[o] - bnm[o] * sc;
            float s = 0.0f;
            for (int p = 0; p < 56; p++) {
                float v = fmaf(sconv[p * 33 + o], sc, sh);
                s += fmaxf(v, 0.0f);
            }
            g_part[b * 32 + o] = s;
        }
    } else {
        // ---------------- pool path (2 planes, MLP-4) ----------------
        int pb  = b - 56;
        int nc0 = pb * PPB;

        if (pb < 83) {                   // w1d center-tap transpose
            int i = pb * 448 + t;
            if (i < 192 * 192) {
                int o = i % 192, cc = i / 192;
                g_w1dT[i] = w1d[o * 576 + cc * 3 + 1];   // [c][o] layout
            }
        }

        if (t < 392) {
            const float4* p = (const float4*)(x + (size_t)nc0 * NPIX) + t * 2;
            float4 a0 = __ldg(p);
            float4 c0 = __ldg(p + 1);
            float4 a1 = __ldg(p + 784);
            float4 c1 = __ldg(p + 785);
            smem[t]       = (a0.x + a0.y + a0.z + a0.w) + (c0.x + c0.y + c0.z + c0.w);
            smem[392 + t] = (a1.x + a1.y + a1.z + a1.w) + (c1.x + c1.y + c1.z + c1.w);
        }
        __syncthreads();
        if (t < 98) {
            int pl = t / 49, cell = t % 49;
            int ci = cell / 7, cj = cell % 7;
            const float* sp = smem + pl * 392 + ci * 56 + cj;
            float s = 0.0f;
#pragma unroll
            for (int u = 0; u < 8; u++) s += sp[u * 7];
            g_xp[(nc0 + pl) * 49 + cell] = s * (1.0f / 64.0f);
        }
    }
}

// ---------------------------------------------------------------------------
// Fused yin+gemm kernel: one block per batch element n (64 blocks, 192 thr).
// Phase A: gate MLP -> param -> DCT basis -> yin[n,:] into SMEM.
// Phase B: y[n,o] = b1d[o] + sum_c w1dT[c,o]*yin[c] (yin from smem broadcast,
//          w1dT coalesced global, unrolled for MLP), BN, ReLU -> g_scale.
// ---------------------------------------------------------------------------
__global__ __launch_bounds__(192) void yingemm_kernel(
    const float* __restrict__ wg2, const float* __restrict__ bg2,
    const float* __restrict__ beta, const float* __restrict__ b1d,
    const float* __restrict__ bn1g, const float* __restrict__ bn1b,
    const float* __restrict__ bn1m, const float* __restrict__ bn1v)
{
    __shared__ float sg[32];
    __shared__ float sxg[32];
    __shared__ float sparam[33];
    __shared__ float sbasis[32 * 49];
    __shared__ float syin[192];

    int n = blockIdx.x, t = threadIdx.x;

    if (t < 32) {
        float s = 0.0f;
        for (int b = 0; b < 56; b++) s += g_part[b * 32 + t];
        sg[t] = s * (1.0f / 3136.0f);
    }
    __syncthreads();
    if (t < 32) {
        float a = bg2[t];
        for (int k = 0; k < 32; k++) a = fmaf(wg2[t * 32 + k], sg[k], a);
        sxg[t] = fmaxf(tanhf(a), 0.0f) + beta[0];
    }
    __syncthreads();
    if (t == 0) {
        float s = 0.0f;
        for (int i = 0; i < 32; i++) s += sxg[i];
        sparam[0] = 0.0f;
        float tot = 0.0f;
        for (int i = 1; i <= 31; i++) {
            float pv = rintf(sxg[i - 1] / s * 192.0f);  // rintf == jnp.round
            sparam[i] = pv;
            tot += pv;
        }
        sparam[32] = 192.0f - tot;
    }
    const float PI = 3.14159265358979323846f;
    const float INV_SQRT7 = 0.37796447300922722721f;
    const float SQRT2 = 1.41421356237309504880f;
    for (int idx = t; idx < 32 * 49; idx += 192) {
        int bi = idx / 49, k = idx % 49;
        int tx = k / 7, ty = k % 7;
        float fx = c_lowx[bi], fy = c_lowy[bi];
        float bx = cosf(PI * fx * (tx + 0.5f) / 7.0f) * INV_SQRT7;
        if (fx != 0.0f) bx *= SQRT2;
        float by = cosf(PI * fy * (ty + 0.5f) / 7.0f) * INV_SQRT7;
        if (fy != 0.0f) by *= SQRT2;
        sbasis[idx] = bx * by;
    }
    __syncthreads();

    // yin[c]: last segment i with param[i] <= c < param[i+1] wins
    {
        float cf = (float)t;
        int bid = -1;
        for (int i = 0; i < 32; i++)
            if (cf >= sparam[i] && cf < sparam[i + 1]) bid = i;
        float yv = 0.0f;
        if (bid >= 0) {
            const float* xpp = g_xp + (n * 192 + t) * 49;
            const float* bb = sbasis + bid * 49;
#pragma unroll
            for (int k = 0; k < 49; k++) yv = fmaf(xpp[k], bb[k], yv);
        }
        syin[t] = yv;
    }
    __syncthreads();

    // GEMV: thread t = output channel o; w reads coalesced, unrolled (MLP 8)
    {
        float a = b1d[t];
        const float* wp = g_w1dT + t;
#pragma unroll 8
        for (int c = 0; c < 192; c++) a = fmaf(__ldg(wp + c * 192), syin[c], a);
        float sc = bn1g[t] / sqrtf(bn1v[t] + 1e-5f);
        a = (a - bn1m[t]) * sc + bn1b[t];
        g_scale[n * 192 + t] = fmaxf(a, 0.0f);
    }
}

// ---------------------------------------------------------------------------
// Final: out = x*(1+scale).  4 independent float4 per thread (MLP-4),
// reverse block order (L2-tail reuse), streaming stores.
// ---------------------------------------------------------------------------
__global__ __launch_bounds__(256) void final_kernel(
    const float* __restrict__ x, float* __restrict__ out)
{
    const float4* x4 = (const float4*)x;
    float4* o4 = (float4*)out;
    int t = threadIdx.x;
    size_t base = (size_t)(FBLK - 1 - blockIdx.x) * FCHUNK;

    float4 v0 = __ldg(x4 + base + t);
    float4 v1 = __ldg(x4 + base + 256 + t);
    float4 v2 = __ldg(x4 + base + 512 + t);
    float4 v3 = __ldg(x4 + base + 768 + t);

    int i0 = (int)(base + t);
    float s0 = 1.0f + __ldg(&g_scale[i0 / 784]);
    float s1 = 1.0f + __ldg(&g_scale[(i0 + 256) / 784]);
    float s2 = 1.0f + __ldg(&g_scale[(i0 + 512) / 784]);
    float s3 = 1.0f + __ldg(&g_scale[(i0 + 768) / 784]);

    v0.x *= s0; v0.y *= s0; v0.z *= s0; v0.w *= s0;
    v1.x *= s1; v1.y *= s1; v1.z *= s1; v1.w *= s1;
    v2.x *= s2; v2.y *= s2; v2.z *= s2; v2.w *= s2;
    v3.x *= s3; v3.y *= s3; v3.z *= s3; v3.w *= s3;

    __stcs(o4 + base + t, v0);
    __stcs(o4 + base + 256 + t, v1);
    __stcs(o4 + base + 512 + t, v2);
    __stcs(o4 + base + 768 + t, v3);
}

// ---------------------------------------------------------------------------
// Inputs (metadata order): x, wg1, bn2_g, bn2_b, bn2_m, bn2_v,
//                          wg2, bg2, beta, w1d, b1d, bn1_g, bn1_b, bn1_m, bn1_v
// ---------------------------------------------------------------------------
extern "C" void kernel_launch(void* const* d_in, const int* in_sizes, int n_in,
                              void* d_out, int out_size)
{
    const float* x     = (const float*)d_in[0];
    const float* wg1   = (const float*)d_in[1];
    const float* bn2g  = (const float*)d_in[2];
    const float* bn2b  = (const float*)d_in[3];
    const float* bn2m  = (const float*)d_in[4];
    const float* bn2v  = (const float*)d_in[5];
    const float* wg2   = (const float*)d_in[6];
    const float* bg2   = (const float*)d_in[7];
    const float* beta  = (const float*)d_in[8];
    const float* w1d   = (const float*)d_in[9];
    const float* b1d   = (const float*)d_in[10];
    const float* bn1g  = (const float*)d_in[11];
    const float* bn1b  = (const float*)d_in[12];
    const float* bn1m  = (const float*)d_in[13];
    const float* bn1v  = (const float*)d_in[14];
    float* out = (float*)d_out;

    poolgate_kernel<<<56 + POOLBLK, 448>>>(x, wg1, bn2g, bn2b, bn2m, bn2v, w1d);
    yingemm_kernel<<<64, 192>>>(wg2, bg2, beta, b1d, bn1g, bn1b, bn1m, bn1v);
    final_kernel<<<FBLK, 256>>>(x, out);
}

// round 14
// speedup vs baseline: 1.0327x; 1.0327x over previous
#include <cuda_runtime.h>
#include <math.h>

#define C_CH   192
#define HW     56
#define NPIX   3136      // 56*56
#define NBATCH 64
#define NPLANE 12288     // 64*192
#define NCELL  602112    // 12288*49
#define N4TOT  9633792   // 64*192*3136/4
#define PPB    2
#define POOLBLK (NPLANE / PPB)   // 6144
#define FCHUNK 1024              // float4 per final block
#define FBLK   (N4TOT / FCHUNK)  // 9408

__constant__ float c_lowx[32] = {0,0,1,1,0,2,2,1,2,0,3,4,0,1,3,0,1,2,3,4,5,0,1,2,3,4,5,6,1,2,3,4};
__constant__ float c_lowy[32] = {0,1,0,1,2,0,1,2,2,3,0,0,4,3,1,5,4,3,2,1,0,6,5,4,3,2,1,0,6,5,4,3};

// Scratch (no allocations allowed -> __device__ globals)
__device__ float g_part[56 * 32];        // per-row gate partial sums (n=0 only)
__device__ float g_xp[NCELL];            // adaptive-avg-pooled x
__device__ float g_w1dT[192 * 192];      // transposed center tap of w1d: [c][o]
__device__ float g_scale[NPLANE];        // final per-(n,c) scale
__device__ int   g_flag;                 // scale-ready arrivals (target 64)
__device__ int   g_done;                 // exit counter; last block resets state

// ---------------------------------------------------------------------------
// Fused gate+pool kernel — EXACT R11 configuration (measured 28.3us, DRAM 71%).
// __launch_bounds__(448,3): 48-reg budget keeps the 4 LDG.128 independent.
// ---------------------------------------------------------------------------
__global__ __launch_bounds__(448, 3) void poolgate_kernel(
    const float* __restrict__ x, const float* __restrict__ wg1,
    const float* __restrict__ bng, const float* __restrict__ bnb,
    const float* __restrict__ bnm, const float* __restrict__ bnv,
    const float* __restrict__ w1d)
{
    __shared__ float smem[192 * 32 + 56 * 33];
    int t = threadIdx.x;
    int b = blockIdx.x;

    if (b < 56) {
        // ---------------- gate path (batch element 0 only) ----------------
        float* sw    = smem;             // [192*32] sw[c*32+o] = wg1[o][c]
        float* sconv = smem + 192 * 32;  // [56*33] padded

        for (int i = t; i < 192 * 32; i += 448) {
            int c = i >> 5, o = i & 31;
            sw[i] = wg1[o * 192 + c];
        }
        for (int i = t; i < 56 * 33; i += 448) sconv[i] = 0.0f;
        __syncthreads();

        int px = t % 56;
        int q  = t / 56;
        const float* xr = x + b * 56 + px;
        float* dst = sconv + px * 33;
        int c0 = q * 24;

        for (int pass = 0; pass < 4; pass++) {
            int o0 = pass * 8;
            float acc[8];
#pragma unroll
            for (int u = 0; u < 8; u++) acc[u] = 0.0f;
#pragma unroll 4
            for (int c = c0; c < c0 + 24; c++) {
                float xv = __ldg(xr + c * NPIX);
                const float* w = sw + c * 32 + o0;
#pragma unroll
                for (int u = 0; u < 8; u++) acc[u] = fmaf(w[u], xv, acc[u]);
            }
#pragma unroll
            for (int u = 0; u < 8; u++) atomicAdd(dst + o0 + u, acc[u]);
        }
        __syncthreads();

        if (t < 32) {
            int o = t;
            float sc = bng[o] / sqrtf(bnv[o] + 1e-5f);
            float sh = bnb[o] - bnm[o] * sc;
            float s = 0.0f;
            for (int p = 0; p < 56; p++) {
                float v = fmaf(sconv[p * 33 + o], sc, sh);
                s += fmaxf(v, 0.0f);
            }
            g_part[b * 32 + o] = s;
        }
    } else {
        // ---------------- pool path (2 planes, MLP-4) ----------------
        int pb  = b - 56;
        int nc0 = pb * PPB;

        if (pb < 83) {                   // w1d center-tap transpose
            int i = pb * 448 + t;
            if (i < 192 * 192) {
                int o = i % 192, cc = i / 192;
                g_w1dT[i] = w1d[o * 576 + cc * 3 + 1];   // [c][o] layout
            }
        }

        if (t < 392) {
            const float4* p = (const float4*)(x + (size_t)nc0 * NPIX) + t * 2;
            float4 a0 = __ldg(p);
            float4 c0 = __ldg(p + 1);
            float4 a1 = __ldg(p + 784);
            float4 c1 = __ldg(p + 785);
            smem[t]       = (a0.x + a0.y + a0.z + a0.w) + (c0.x + c0.y + c0.z + c0.w);
            smem[392 + t] = (a1.x + a1.y + a1.z + a1.w) + (c1.x + c1.y + c1.z + c1.w);
        }
        __syncthreads();
        if (t < 98) {
            int pl = t / 49, cell = t % 49;
            int ci = cell / 7, cj = cell % 7;
            const float* sp = smem + pl * 392 + ci * 56 + cj;
            float s = 0.0f;
#pragma unroll
            for (int u = 0; u < 8; u++) s += sp[u * 7];
            g_xp[(nc0 + pl) * 49 + cell] = s * (1.0f / 64.0f);
        }
    }
}

// ---------------------------------------------------------------------------
// Fused scale+final kernel (one graph node instead of two).
//   All blocks: prefetch their 4 x-float4 FIRST (overlaps scale compute).
//   Blocks 0..63: compute scale row n=b (gate MLP -> param -> basis -> yin ->
//                 GEMV -> BN/ReLU), publish, arrive on g_flag.
//   All blocks: spin until g_flag==64, then multiply+streaming-store.
//   Last exiting block resets g_flag/g_done for deterministic graph replays.
// Blocks 0..63 are in wave 1 of a 9408-block launch -> no deadlock.
// ---------------------------------------------------------------------------
__global__ __launch_bounds__(256) void scalefinal_kernel(
    const float* __restrict__ x, float* __restrict__ out,
    const float* __restrict__ wg2, const float* __restrict__ bg2,
    const float* __restrict__ beta, const float* __restrict__ b1d,
    const float* __restrict__ bn1g, const float* __restrict__ bn1b,
    const float* __restrict__ bn1m, const float* __restrict__ bn1v)
{
    __shared__ float sg[32];
    __shared__ float sxg[32];
    __shared__ float sparam[33];
    __shared__ float sbasis[32 * 49];
    __shared__ float syin[192];

    int t = threadIdx.x;
    int b = blockIdx.x;

    const float4* x4 = (const float4*)x;
    float4* o4 = (float4*)out;
    size_t base = (size_t)(FBLK - 1 - b) * FCHUNK;   // reverse order: L2-tail reuse

    // ---- prefetch x into registers (in flight during scale compute/spin) ----
    float4 v0 = __ldg(x4 + base + t);
    float4 v1 = __ldg(x4 + base + 256 + t);
    float4 v2 = __ldg(x4 + base + 512 + t);
    float4 v3 = __ldg(x4 + base + 768 + t);

    // ---- scale phase (blocks 0..63 only; n = b) ----
    if (b < 64) {
        int n = b;
        if (t < 32) {
            float s = 0.0f;
            for (int r = 0; r < 56; r++) s += g_part[r * 32 + t];
            sg[t] = s * (1.0f / 3136.0f);
        }
        __syncthreads();
        if (t < 32) {
            float a = bg2[t];
            for (int k = 0; k < 32; k++) a = fmaf(wg2[t * 32 + k], sg[k], a);
            sxg[t] = fmaxf(tanhf(a), 0.0f) + beta[0];
        }
        __syncthreads();
        if (t == 0) {
            float s = 0.0f;
            for (int i = 0; i < 32; i++) s += sxg[i];
            sparam[0] = 0.0f;
            float tot = 0.0f;
            for (int i = 1; i <= 31; i++) {
                float pv = rintf(sxg[i - 1] / s * 192.0f);  // == jnp.round
                sparam[i] = pv;
                tot += pv;
            }
            sparam[32] = 192.0f - tot;
        }
        const float PI = 3.14159265358979323846f;
        const float INV_SQRT7 = 0.37796447300922722721f;
        const float SQRT2 = 1.41421356237309504880f;
        for (int idx = t; idx < 32 * 49; idx += 256) {
            int bi = idx / 49, k = idx % 49;
            int tx = k / 7, ty = k % 7;
            float fx = c_lowx[bi], fy = c_lowy[bi];
            float bx = cosf(PI * fx * (tx + 0.5f) / 7.0f) * INV_SQRT7;
            if (fx != 0.0f) bx *= SQRT2;
            float by = cosf(PI * fy * (ty + 0.5f) / 7.0f) * INV_SQRT7;
            if (fy != 0.0f) by *= SQRT2;
            sbasis[idx] = bx * by;
        }
        __syncthreads();

        if (t < 192) {                    // yin[c]: last matching segment wins
            float cf = (float)t;
            int bid = -1;
            for (int i = 0; i < 32; i++)
                if (cf >= sparam[i] && cf < sparam[i + 1]) bid = i;
            float yv = 0.0f;
            if (bid >= 0) {
                const float* xpp = g_xp + (n * 192 + t) * 49;
                const float* bb = sbasis + bid * 49;
#pragma unroll
                for (int k = 0; k < 49; k++) yv = fmaf(__ldcg(xpp + k), bb[k], yv);
            }
            syin[t] = yv;
        }
        __syncthreads();

        if (t < 192) {                    // GEMV, w1dT coalesced, MLP-8
            float a = b1d[t];
            const float* wp = g_w1dT + t;
#pragma unroll 8
            for (int c = 0; c < 192; c++) a = fmaf(__ldcg(wp + c * 192), syin[c], a);
            float sc = bn1g[t] / sqrtf(bn1v[t] + 1e-5f);
            a = (a - bn1m[t]) * sc + bn1b[t];
            g_scale[n * 192 + t] = fmaxf(a, 0.0f);
        }
        __threadfence();
        __syncthreads();
        if (t == 0) atomicAdd(&g_flag, 1);
    }

    // ---- wait for all 64 scale rows ----
    if (t == 0) {
        while (*(volatile int*)&g_flag < 64) __nanosleep(64);
    }
    __syncthreads();

    // ---- final multiply + streaming store ----
    {
        int i0 = (int)(base + t);
        float s0 = 1.0f + __ldcg(&g_scale[i0 / 784]);
        float s1 = 1.0f + __ldcg(&g_scale[(i0 + 256) / 784]);
        float s2 = 1.0f + __ldcg(&g_scale[(i0 + 512) / 784]);
        float s3 = 1.0f + __ldcg(&g_scale[(i0 + 768) / 784]);

        v0.x *= s0; v0.y *= s0; v0.z *= s0; v0.w *= s0;
        v1.x *= s1; v1.y *= s1; v1.z *= s1; v1.w *= s1;
        v2.x *= s2; v2.y *= s2; v2.z *= s2; v2.w *= s2;
        v3.x *= s3; v3.y *= s3; v3.z *= s3; v3.w *= s3;

        __stcs(o4 + base + t, v0);
        __stcs(o4 + base + 256 + t, v1);
        __stcs(o4 + base + 512 + t, v2);
        __stcs(o4 + base + 768 + t, v3);
    }

    // ---- reset sync state for next graph replay (last block only) ----
    if (t == 0) {
        int v = atomicAdd(&g_done, 1);
        if (v == FBLK - 1) {
            g_flag = 0;
            g_done = 0;
            __threadfence();
        }
    }
}

// ---------------------------------------------------------------------------
// Inputs (metadata order): x, wg1, bn2_g, bn2_b, bn2_m, bn2_v,
//                          wg2, bg2, beta, w1d, b1d, bn1_g, bn1_b, bn1_m, bn1_v
// ---------------------------------------------------------------------------
extern "C" void kernel_launch(void* const* d_in, const int* in_sizes, int n_in,
                              void* d_out, int out_size)
{
    const float* x     = (const float*)d_in[0];
    const float* wg1   = (const float*)d_in[1];
    const float* bn2g  = (const float*)d_in[2];
    const float* bn2b  = (const float*)d_in[3];
    const float* bn2m  = (const float*)d_in[4];
    const float* bn2v  = (const float*)d_in[5];
    const float* wg2   = (const float*)d_in[6];
    const float* bg2   = (const float*)d_in[7];
    const float* beta  = (const float*)d_in[8];
    const float* w1d   = (const float*)d_in[9];
    const float* b1d   = (const float*)d_in[10];
    const float* bn1g  = (const float*)d_in[11];
    const float* bn1b  = (const float*)d_in[12];
    const float* bn1m  = (const float*)d_in[13];
    const float* bn1v  = (const float*)d_in[14];
    float* out = (float*)d_out;

    poolgate_kernel<<<56 + POOLBLK, 448>>>(x, wg1, bn2g, bn2b, bn2m, bn2v, w1d);
    scalefinal_kernel<<<FBLK, 256>>>(x, out, wg2, bg2, beta, b1d,
                                     bn1g, bn1b, bn1m, bn1v);
}

// round 15
// speedup vs baseline: 1.0887x; 1.0541x over previous
#include <cuda_runtime.h>
#include <math.h>

#define C_CH   192
#define HW     56
#define NPIX   3136      // 56*56
#define NBATCH 64
#define NPLANE 12288     // 64*192
#define NCELL  602112    // 12288*49
#define N4TOT  9633792   // 64*192*3136/4
#define PPB    2
#define POOLBLK (NPLANE / PPB)   // 6144
#define FCHUNK 1024              // float4 per copy block
#define FBLK   (N4TOT / FCHUNK)  // 9408
#define K2BLK  (64 + FBLK)       // kernel-2 grid

__constant__ float c_lowx[32] = {0,0,1,1,0,2,2,1,2,0,3,4,0,1,3,0,1,2,3,4,5,0,1,2,3,4,5,6,1,2,3,4};
__constant__ float c_lowy[32] = {0,1,0,1,2,0,1,2,2,3,0,0,4,3,1,5,4,3,2,1,0,6,5,4,3,2,1,0,6,5,4,3};

// Scratch (no allocations allowed -> __device__ globals)
__device__ float g_part[56 * 32];        // per-row gate partial sums (n=0 only)
__device__ float g_xp[NCELL];            // adaptive-avg-pooled x
__device__ float g_w1dT[192 * 192];      // transposed center tap of w1d: [c][o]
__device__ float g_scale[NPLANE];        // final per-(n,c) scale
__device__ int   g_flag;                 // scale-ready arrivals (target 64)
__device__ int   g_done;                 // exit counter; last block resets state

// ---------------------------------------------------------------------------
// Fused gate+pool kernel — EXACT R11 configuration (measured 28.3us, DRAM 71%).
// __launch_bounds__(448,3): 48-reg budget keeps the 4 LDG.128 independent.
// ---------------------------------------------------------------------------
__global__ __launch_bounds__(448, 3) void poolgate_kernel(
    const float* __restrict__ x, const float* __restrict__ wg1,
    const float* __restrict__ bng, const float* __restrict__ bnb,
    const float* __restrict__ bnm, const float* __restrict__ bnv,
    const float* __restrict__ w1d)
{
    __shared__ float smem[192 * 32 + 56 * 33];
    int t = threadIdx.x;
    int b = blockIdx.x;

    if (b < 56) {
        // ---------------- gate path (batch element 0 only) ----------------
        float* sw    = smem;             // [192*32] sw[c*32+o] = wg1[o][c]
        float* sconv = smem + 192 * 32;  // [56*33] padded

        for (int i = t; i < 192 * 32; i += 448) {
            int c = i >> 5, o = i & 31;
            sw[i] = wg1[o * 192 + c];
        }
        for (int i = t; i < 56 * 33; i += 448) sconv[i] = 0.0f;
        __syncthreads();

        int px = t % 56;
        int q  = t / 56;
        const float* xr = x + b * 56 + px;
        float* dst = sconv + px * 33;
        int c0 = q * 24;

        for (int pass = 0; pass < 4; pass++) {
            int o0 = pass * 8;
            float acc[8];
#pragma unroll
            for (int u = 0; u < 8; u++) acc[u] = 0.0f;
#pragma unroll 4
            for (int c = c0; c < c0 + 24; c++) {
                float xv = __ldg(xr + c * NPIX);
                const float* w = sw + c * 32 + o0;
#pragma unroll
                for (int u = 0; u < 8; u++) acc[u] = fmaf(w[u], xv, acc[u]);
            }
#pragma unroll
            for (int u = 0; u < 8; u++) atomicAdd(dst + o0 + u, acc[u]);
        }
        __syncthreads();

        if (t < 32) {
            int o = t;
            float sc = bng[o] / sqrtf(bnv[o] + 1e-5f);
            float sh = bnb[o] - bnm[o] * sc;
            float s = 0.0f;
            for (int p = 0; p < 56; p++) {
                float v = fmaf(sconv[p * 33 + o], sc, sh);
                s += fmaxf(v, 0.0f);
            }
            g_part[b * 32 + o] = s;
        }
    } else {
        // ---------------- pool path (2 planes, MLP-4) ----------------
        int pb  = b - 56;
        int nc0 = pb * PPB;

        if (pb < 83) {                   // w1d center-tap transpose
            int i = pb * 448 + t;
            if (i < 192 * 192) {
                int o = i % 192, cc = i / 192;
                g_w1dT[i] = w1d[o * 576 + cc * 3 + 1];   // [c][o] layout
            }
        }

        if (t < 392) {
            const float4* p = (const float4*)(x + (size_t)nc0 * NPIX) + t * 2;
            float4 a0 = __ldg(p);
            float4 c0 = __ldg(p + 1);
            float4 a1 = __ldg(p + 784);
            float4 c1 = __ldg(p + 785);
            smem[t]       = (a0.x + a0.y + a0.z + a0.w) + (c0.x + c0.y + c0.z + c0.w);
            smem[392 + t] = (a1.x + a1.y + a1.z + a1.w) + (c1.x + c1.y + c1.z + c1.w);
        }
        __syncthreads();
        if (t < 98) {
            int pl = t / 49, cell = t % 49;
            int ci = cell / 7, cj = cell % 7;
            const float* sp = smem + pl * 392 + ci * 56 + cj;
            float s = 0.0f;
#pragma unroll
            for (int u = 0; u < 8; u++) s += sp[u * 7];
            g_xp[(nc0 + pl) * 49 + cell] = s * (1.0f / 64.0f);
        }
    }
}

// ---------------------------------------------------------------------------
// Kernel 2: DISJOINT block roles (no register set live across both phases).
//   blocks 0..63   : scale row n=b (gate MLP -> param -> basis -> yin -> GEMV
//                    -> BN/ReLU) -> g_scale; arrive on g_flag; exit.
//   blocks 64..    : copy chunk; prefetch 4 x-float4 (MLP-4), spin on g_flag,
//                    multiply, streaming store. Reverse order for L2-tail hits.
// Blocks 0..63 are first in issue order -> resident in wave 1 -> no deadlock.
// Last exiting block resets g_flag/g_done (deterministic graph replays).
// ---------------------------------------------------------------------------
__global__ __launch_bounds__(256, 6) void scalefinal_kernel(
    const float* __restrict__ x, float* __restrict__ out,
    const float* __restrict__ wg2, const float* __restrict__ bg2,
    const float* __restrict__ beta, const float* __restrict__ b1d,
    const float* __restrict__ bn1g, const float* __restrict__ bn1b,
    const float* __restrict__ bn1m, const float* __restrict__ bn1v)
{
    int t = threadIdx.x;
    int b = blockIdx.x;

    if (b < 64) {
        // ================= scale path =================
        __shared__ float sg[32];
        __shared__ float sxg[32];
        __shared__ float sparam[33];
        __shared__ float sbasis[32 * 49];
        __shared__ float syin[192];

        int n = b;
        if (t < 32) {
            float s = 0.0f;
            for (int r = 0; r < 56; r++) s += g_part[r * 32 + t];
            sg[t] = s * (1.0f / 3136.0f);
        }
        __syncthreads();
        if (t < 32) {
            float a = bg2[t];
            for (int k = 0; k < 32; k++) a = fmaf(wg2[t * 32 + k], sg[k], a);
            sxg[t] = fmaxf(tanhf(a), 0.0f) + beta[0];
        }
        __syncthreads();
        if (t == 0) {
            float s = 0.0f;
            for (int i = 0; i < 32; i++) s += sxg[i];
            sparam[0] = 0.0f;
            float tot = 0.0f;
            for (int i = 1; i <= 31; i++) {
                float pv = rintf(sxg[i - 1] / s * 192.0f);  // == jnp.round
                sparam[i] = pv;
                tot += pv;
            }
            sparam[32] = 192.0f - tot;
        }
        const float PI = 3.14159265358979323846f;
        const float INV_SQRT7 = 0.37796447300922722721f;
        const float SQRT2 = 1.41421356237309504880f;
        for (int idx = t; idx < 32 * 49; idx += 256) {
            int bi = idx / 49, k = idx % 49;
            int tx = k / 7, ty = k % 7;
            float fx = c_lowx[bi], fy = c_lowy[bi];
            float bx = cosf(PI * fx * (tx + 0.5f) / 7.0f) * INV_SQRT7;
            if (fx != 0.0f) bx *= SQRT2;
            float by = cosf(PI * fy * (ty + 0.5f) / 7.0f) * INV_SQRT7;
            if (fy != 0.0f) by *= SQRT2;
            sbasis[idx] = bx * by;
        }
        __syncthreads();

        if (t < 192) {                    // yin[c]: last matching segment wins
            float cf = (float)t;
            int bid = -1;
            for (int i = 0; i < 32; i++)
                if (cf >= sparam[i] && cf < sparam[i + 1]) bid = i;
            float yv = 0.0f;
            if (bid >= 0) {
                const float* xpp = g_xp + (n * 192 + t) * 49;
                const float* bb = sbasis + bid * 49;
#pragma unroll
                for (int k = 0; k < 49; k++) yv = fmaf(xpp[k], bb[k], yv);
            }
            syin[t] = yv;
        }
        __syncthreads();

        if (t < 192) {                    // GEMV, w1dT coalesced, MLP-8
            float a = b1d[t];
            const float* wp = g_w1dT + t;
#pragma unroll 8
            for (int c = 0; c < 192; c++) a = fmaf(__ldg(wp + c * 192), syin[c], a);
            float sc = bn1g[t] / sqrtf(bn1v[t] + 1e-5f);
            a = (a - bn1m[t]) * sc + bn1b[t];
            g_scale[n * 192 + t] = fmaxf(a, 0.0f);
        }
        __threadfence();
        __syncthreads();
        if (t == 0) atomicAdd(&g_flag, 1);
    } else {
        // ================= copy path =================
        const float4* x4 = (const float4*)x;
        float4* o4 = (float4*)out;
        int cb = b - 64;
        size_t base = (size_t)(FBLK - 1 - cb) * FCHUNK;   // reverse order

        // prefetch (in flight while scale blocks finish)
        float4 v0 = __ldg(x4 + base + t);
        float4 v1 = __ldg(x4 + base + 256 + t);
        float4 v2 = __ldg(x4 + base + 512 + t);
        float4 v3 = __ldg(x4 + base + 768 + t);

        if (t == 0) {
            while (*(volatile int*)&g_flag < 64) __nanosleep(64);
        }
        __syncthreads();

        int i0 = (int)(base + t);
        float s0 = 1.0f + __ldcg(&g_scale[i0 / 784]);
        float s1 = 1.0f + __ldcg(&g_scale[(i0 + 256) / 784]);
        float s2 = 1.0f + __ldcg(&g_scale[(i0 + 512) / 784]);
        float s3 = 1.0f + __ldcg(&g_scale[(i0 + 768) / 784]);

        v0.x *= s0; v0.y *= s0; v0.z *= s0; v0.w *= s0;
        v1.x *= s1; v1.y *= s1; v1.z *= s1; v1.w *= s1;
        v2.x *= s2; v2.y *= s2; v2.z *= s2; v2.w *= s2;
        v3.x *= s3; v3.y *= s3; v3.z *= s3; v3.w *= s3;

        __stcs(o4 + base + t, v0);
        __stcs(o4 + base + 256 + t, v1);
        __stcs(o4 + base + 512 + t, v2);
        __stcs(o4 + base + 768 + t, v3);
    }

    // ---- reset sync state for next graph replay (last block only) ----
    if (t == 0) {
        int v = atomicAdd(&g_done, 1);
        if (v == K2BLK - 1) {
            g_flag = 0;
            g_done = 0;
            __threadfence();
        }
    }
}

// ---------------------------------------------------------------------------
// Inputs (metadata order): x, wg1, bn2_g, bn2_b, bn2_m, bn2_v,
//                          wg2, bg2, beta, w1d, b1d, bn1_g, bn1_b, bn1_m, bn1_v
// ---------------------------------------------------------------------------
extern "C" void kernel_launch(void* const* d_in, const int* in_sizes, int n_in,
                              void* d_out, int out_size)
{
    const float* x     = (const float*)d_in[0];
    const float* wg1   = (const float*)d_in[1];
    const float* bn2g  = (const float*)d_in[2];
    const float* bn2b  = (const float*)d_in[3];
    const float* bn2m  = (const float*)d_in[4];
    const float* bn2v  = (const float*)d_in[5];
    const float* wg2   = (const float*)d_in[6];
    const float* bg2   = (const float*)d_in[7];
    const float* beta  = (const float*)d_in[8];
    const float* w1d   = (const float*)d_in[9];
    const float* b1d   = (const float*)d_in[10];
    const float* bn1g  = (const float*)d_in[11];
    const float* bn1b  = (const float*)d_in[12];
    const float* bn1m  = (const float*)d_in[13];
    const float* bn1v  = (const float*)d_in[14];
    float* out = (float*)d_out;

    poolgate_kernel<<<56 + POOLBLK, 448>>>(x, wg1, bn2g, bn2b, bn2m, bn2v, w1d);
    scalefinal_kernel<<<K2BLK, 256>>>(x, out, wg2, bg2, beta, b1d,
                                      bn1g, bn1b, bn1m, bn1v);
}